// round 2
// baseline (speedup 1.0000x reference)
#include <cuda_runtime.h>
#include <cstdint>

// Problem constants
#define B_    128
#define CIN_  64
#define NF_   16
#define COUT_ 256
#define H_    20
#define W_    20
#define HW_   400
#define M_    (B_*HW_)    // 51200
#define K_    (CIN_*NF_)  // 1024

// GEMM tiling
#define BM 128
#define BN 256
#define BK 16
#define TM 8
#define TN 16

// ---------------- scratch (static __device__, no allocations) ----------------
__device__ __align__(16) float  g_xt[B_*HW_*CIN_];    // x transposed: [b][pix][cin], 13.1MB
__device__ __align__(16) float  g_comb2[K_*COUT_];    // comb reordered+transposed: [k'][o], k'=nf*64+cin
__device__ __align__(16) int4   g_off[NF_*HW_];       // 4 gather offsets per (nf,pix)
__device__ __align__(16) float4 g_w[NF_*HW_];         // 4 bilinear weights per (nf,pix)

// ---------------- packed f32x2 helpers ----------------
__device__ __forceinline__ unsigned long long pack2(float a, float b) {
    unsigned long long r;
    asm("mov.b64 %0, {%1, %2};" : "=l"(r) : "f"(a), "f"(b));
    return r;
}
__device__ __forceinline__ void unpack2(unsigned long long v, float& a, float& b) {
    asm("mov.b64 {%0, %1}, %2;" : "=f"(a), "=f"(b) : "l"(v));
}
__device__ __forceinline__ void ffma2(unsigned long long& d, unsigned long long a, unsigned long long b) {
    asm("fma.rn.f32x2 %0, %1, %2, %0;" : "+l"(d) : "l"(a), "l"(b));
}

// ---------------- setup kernel 1: transpose x -> x_t[b][pix][cin] ----------------
__global__ void k_transpose_x(const float* __restrict__ x) {
    __shared__ float tile[32][33];
    int b    = blockIdx.z;
    int pix0 = blockIdx.x * 32;
    int cin0 = blockIdx.y * 32;
    int tx = threadIdx.x, ty = threadIdx.y;  // 32 x 8
#pragma unroll
    for (int k = 0; k < 4; k++) {
        int cin = cin0 + ty + k * 8;
        int pix = pix0 + tx;
        float v = 0.0f;
        if (pix < HW_) v = x[(b * CIN_ + cin) * HW_ + pix];
        tile[ty + k * 8][tx] = v;
    }
    __syncthreads();
#pragma unroll
    for (int k = 0; k < 4; k++) {
        int pix = pix0 + ty + k * 8;
        int cin = cin0 + tx;
        if (pix < HW_) g_xt[(b * HW_ + pix) * CIN_ + cin] = tile[tx][ty + k * 8];
    }
}

// ---------------- setup kernel 2: comb -> comb2[k'][o], k'=nf*64+cin ----------------
__global__ void k_comb(const float* __restrict__ comb) {
    int t  = blockIdx.x * 256 + threadIdx.x;   // over K_*COUT_
    int o  = t & 255;
    int kp = t >> 8;
    int nf  = kp >> 6;
    int cin = kp & 63;
    g_comb2[t] = comb[o * K_ + cin * NF_ + nf];
}

// ---------------- setup kernel 3: bilinear gather table ----------------
__device__ __forceinline__ void make_corner(int ix, int iy, float w, int& off, float& wo) {
    int cx = min(max(ix, 0), H_);   // clip(ix, 0, r)
    int cy = min(max(iy, 0), W_);   // clip(iy, 0, c)
    // padded[cx+1][cy+1]: zero if cx==H_ or cy==W_, else x[cx][cy]
    if (cx < H_ && cy < W_) { off = cx * W_ + cy; wo = w; }
    else                    { off = 0;            wo = 0.0f; }
}

__global__ void k_table(const float* __restrict__ flow) {
    int t = blockIdx.x * 128 + threadIdx.x;
    if (t >= NF_ * HW_) return;
    int pix = t % HW_;
    int i = pix / W_, j = pix % W_;
    float f0 = flow[2 * t + 0];
    float f1 = flow[2 * t + 1];
    float ixf = (float)i + f0;
    float iyf = (float)j + f1;
    float bxf = floorf(ixf), byf = floorf(iyf);
    float s  = ixf - bxf;
    float tt = iyf - byf;
    int bx = (int)bxf, by = (int)byf;
    // NOTE: w10 = s*(1-t) replicates the reference's (intentional) bug.
    float w00 = (1.0f - s) * (1.0f - tt);
    float w01 = s * (1.0f - tt);
    float w10 = s * (1.0f - tt);
    float w11 = s * tt;
    int4 off; float4 wv;
    make_corner(bx,     by,     w00, off.x, wv.x);
    make_corner(bx + 1, by,     w01, off.y, wv.y);
    make_corner(bx,     by + 1, w10, off.z, wv.z);
    make_corner(bx + 1, by + 1, w11, off.w, wv.w);
    g_off[t] = off;
    g_w[t]   = wv;
}

// ---------------- fused gather + GEMM ----------------
// out[b][o][pix] = sum_{k'} feat[row][k'] * comb2[k'][o] + bias[o]
// row = b*400+pix, k' = nf*64+cin, feat = bilinear-warped x.
__global__ __launch_bounds__(256, 1) void k_gemm(const float* __restrict__ bias,
                                                 float* __restrict__ out) {
    __shared__ __align__(16) float feats[BK][BM];   // 8KB
    __shared__ __align__(16) float combs[BK][BN];   // 16KB

    int m0  = blockIdx.x * BM;
    int tid = threadIdx.x;
    int tx = tid & 15;    // M direction (16 groups x TM=8, interleaved by 16)
    int ty = tid >> 4;    // N direction (16 groups x TN=16, interleaved by 16)

    unsigned long long acc[TM][TN / 2];
#pragma unroll
    for (int i = 0; i < TM; i++)
#pragma unroll
        for (int j = 0; j < TN / 2; j++) acc[i][j] = 0ull;

    // two build items per thread: (row, cin-quad q)
    int e0 = tid, e1 = tid + 256;
    int row0 = e0 & 127, q0 = e0 >> 7;       // q0 in {0,1}
    int row1 = e1 & 127, q1 = e1 >> 7;       // q1 in {2,3}
    int rg0 = m0 + row0, rg1 = m0 + row1;
    int b0 = rg0 / HW_, pix0 = rg0 - b0 * HW_;
    int b1 = rg1 / HW_, pix1 = rg1 - b1 * HW_;
    const float* xb0 = g_xt + (size_t)b0 * HW_ * CIN_ + q0 * 4;
    const float* xb1 = g_xt + (size_t)b1 * HW_ * CIN_ + q1 * 4;

    int4 off0, off1; float4 w0, w1;

    for (int ks = 0; ks < K_ / BK; ks++) {     // 64 K-steps
        int nf = ks >> 2;                      // each chunk: one nf, 16 cin
        int c0 = (ks & 3) << 4;
        if ((ks & 3) == 0) {                   // table reused across 4 K-steps
            off0 = g_off[nf * HW_ + pix0];  w0 = g_w[nf * HW_ + pix0];
            off1 = g_off[nf * HW_ + pix1];  w1 = g_w[nf * HW_ + pix1];
        }
        // build feat tile (bilinear gather, vectorized over cin)
        {
            const float* p = xb0 + c0;
            float4 v0 = *(const float4*)(p + (size_t)off0.x * CIN_);
            float4 v1 = *(const float4*)(p + (size_t)off0.y * CIN_);
            float4 v2 = *(const float4*)(p + (size_t)off0.z * CIN_);
            float4 v3 = *(const float4*)(p + (size_t)off0.w * CIN_);
            feats[q0 * 4 + 0][row0] = w0.x * v0.x + w0.y * v1.x + w0.z * v2.x + w0.w * v3.x;
            feats[q0 * 4 + 1][row0] = w0.x * v0.y + w0.y * v1.y + w0.z * v2.y + w0.w * v3.y;
            feats[q0 * 4 + 2][row0] = w0.x * v0.z + w0.y * v1.z + w0.z * v2.z + w0.w * v3.z;
            feats[q0 * 4 + 3][row0] = w0.x * v0.w + w0.y * v1.w + w0.z * v2.w + w0.w * v3.w;
        }
        {
            const float* p = xb1 + c0;
            float4 v0 = *(const float4*)(p + (size_t)off1.x * CIN_);
            float4 v1 = *(const float4*)(p + (size_t)off1.y * CIN_);
            float4 v2 = *(const float4*)(p + (size_t)off1.z * CIN_);
            float4 v3 = *(const float4*)(p + (size_t)off1.w * CIN_);
            feats[q1 * 4 + 0][row1] = w1.x * v0.x + w1.y * v1.x + w1.z * v2.x + w1.w * v3.x;
            feats[q1 * 4 + 1][row1] = w1.x * v0.y + w1.y * v1.y + w1.z * v2.y + w1.w * v3.y;
            feats[q1 * 4 + 2][row1] = w1.x * v0.z + w1.y * v1.z + w1.z * v2.z + w1.w * v3.z;
            feats[q1 * 4 + 3][row1] = w1.x * v0.w + w1.y * v1.w + w1.z * v2.w + w1.w * v3.w;
        }
        // load comb tile (contiguous 16KB, coalesced)
        {
            const float* cg = g_comb2 + (size_t)ks * (BK * BN);
            float* cs = &combs[0][0];
#pragma unroll
            for (int c = 0; c < 4; c++) {
                *(float4*)(cs + c * 1024 + tid * 4) = *(const float4*)(cg + c * 1024 + tid * 4);
            }
        }
        __syncthreads();
#pragma unroll
        for (int kk = 0; kk < BK; kk++) {
            float a[TM];
#pragma unroll
            for (int i = 0; i < TM; i++) a[i] = feats[kk][i * 16 + tx];
            unsigned long long bb[TN / 2];
#pragma unroll
            for (int j = 0; j < TN / 2; j++)
                bb[j] = pack2(combs[kk][(2 * j) * 16 + ty], combs[kk][(2 * j + 1) * 16 + ty]);
#pragma unroll
            for (int i = 0; i < TM; i++) {
                unsigned long long a2 = pack2(a[i], a[i]);
#pragma unroll
                for (int j = 0; j < TN / 2; j++) ffma2(acc[i][j], a2, bb[j]);
            }
        }
        __syncthreads();
    }

    // epilogue: += bias, write out[b][o][pix]
    float bv[TN];
#pragma unroll
    for (int j = 0; j < TN; j++) bv[j] = bias[j * 16 + ty];
#pragma unroll
    for (int i = 0; i < TM; i++) {
        int r   = m0 + i * 16 + tx;
        int b   = r / HW_;
        int pix = r - b * HW_;
        float* ob = out + (size_t)b * COUT_ * HW_ + pix;
#pragma unroll
        for (int j = 0; j < TN / 2; j++) {
            float v0, v1;
            unpack2(acc[i][j], v0, v1);
            int o0 = (2 * j) * 16 + ty;
            int o1 = (2 * j + 1) * 16 + ty;
            ob[(size_t)o0 * HW_] = v0 + bv[2 * j];
            ob[(size_t)o1 * HW_] = v1 + bv[2 * j + 1];
        }
    }
}

// ---------------- launch ----------------
extern "C" void kernel_launch(void* const* d_in, const int* in_sizes, int n_in,
                              void* d_out, int out_size) {
    const float* x    = nullptr;
    const float* flow = nullptr;
    const float* comb = nullptr;
    const float* bias = nullptr;
    for (int i = 0; i < n_in; i++) {
        switch (in_sizes[i]) {
            case B_ * CIN_ * HW_: x    = (const float*)d_in[i]; break;  // 2,048,000
            case NF_ * HW_ * 2:   flow = (const float*)d_in[i]; break;  // 12,800
            case COUT_ * K_:      comb = (const float*)d_in[i]; break;  // 262,144
            case COUT_:           bias = (const float*)d_in[i]; break;  // 256
            default: break;
        }
    }
    float* out = (float*)d_out;

    // setup
    {
        dim3 blk(32, 8);
        dim3 grd((HW_ + 31) / 32, CIN_ / 32, B_);   // (13, 2, 128)
        k_transpose_x<<<grd, blk>>>(x);
    }
    k_comb<<<(K_ * COUT_) / 256, 256>>>(comb);
    k_table<<<(NF_ * HW_ + 127) / 128, 128>>>(flow);

    // fused gather + GEMM
    k_gemm<<<M_ / BM, 256>>>(bias, out);
}

// round 14
// speedup vs baseline: 1.9346x; 1.9346x over previous
#include <cuda_runtime.h>
#include <cuda_bf16.h>
#include <cstdint>

// Problem constants
#define B_    128
#define CIN_  64
#define NF_   16
#define COUT_ 256
#define H_    20
#define W_    20
#define HW_   400
#define M_    (B_*HW_)    // 51200
#define K_    (CIN_*NF_)  // 1024

// Tile config
#define BM    64          // rows per CTA
#define BN    256         // full COUT
#define KC    64          // K chunk = one nf
#define NCHUNK 16
#define RSTRIDE 144       // smem row stride bytes (72 bf16: 64 data + 8 pad)

// SMEM layout (bytes)
#define OFF_BIAS 0                       // 256 floats = 1024
#define OFF_AHI  1024                    // 64 rows x 144B = 9216
#define OFF_ALO  (OFF_AHI + 9216)
#define OFF_BHI  (OFF_ALO + 9216)        // 256 rows x 144B = 36864
#define OFF_BLO  (OFF_BHI + 36864)
#define SMEM_TOTAL (OFF_BLO + 36864)     // 93184 B

// ---------------- scratch (static __device__, no allocations) ----------------
__device__ __align__(16) float  g_xt[B_*HW_*CIN_];          // x transposed: [b][pix][cin]
__device__ __align__(16) __nv_bfloat16 g_cb_hi[NCHUNK*COUT_*KC]; // comb hi: [nf][o][cin]
__device__ __align__(16) __nv_bfloat16 g_cb_lo[NCHUNK*COUT_*KC]; // comb lo
__device__ __align__(16) int4   g_off[NF_*HW_];             // 4 gather offsets per (nf,pix)
__device__ __align__(16) float4 g_w[NF_*HW_];               // 4 bilinear weights per (nf,pix)

// ---------------- PTX helpers (baseline sm_103: mma.sync + ldmatrix only) ----------------
__device__ __forceinline__ uint32_t smem_u32(const void* p) {
    uint32_t a;
    asm("{ .reg .u64 t; cvta.to.shared.u64 t, %1; cvt.u32.u64 %0, t; }" : "=r"(a) : "l"(p));
    return a;
}
__device__ __forceinline__ void ldm_x4(uint32_t& r0, uint32_t& r1, uint32_t& r2, uint32_t& r3,
                                       uint32_t addr) {
    asm volatile("ldmatrix.sync.aligned.m8n8.x4.shared.b16 {%0,%1,%2,%3}, [%4];"
                 : "=r"(r0), "=r"(r1), "=r"(r2), "=r"(r3) : "r"(addr));
}
__device__ __forceinline__ void mma_bf16(float* c, uint32_t a0, uint32_t a1, uint32_t a2,
                                         uint32_t a3, uint32_t b0, uint32_t b1) {
    asm volatile(
        "mma.sync.aligned.m16n8k16.row.col.f32.bf16.bf16.f32 "
        "{%0,%1,%2,%3}, {%4,%5,%6,%7}, {%8,%9}, {%0,%1,%2,%3};"
        : "+f"(c[0]), "+f"(c[1]), "+f"(c[2]), "+f"(c[3])
        : "r"(a0), "r"(a1), "r"(a2), "r"(a3), "r"(b0), "r"(b1));
}
__device__ __forceinline__ void sts_v2(uint32_t addr, uint32_t a, uint32_t b) {
    asm volatile("st.shared.v2.b32 [%0], {%1, %2};" :: "r"(addr), "r"(a), "r"(b) : "memory");
}

// ---------------- setup kernel 1: transpose x -> x_t[b][pix][cin] ----------------
__global__ void k_transpose_x(const float* __restrict__ x) {
    __shared__ float tile[32][33];
    int b    = blockIdx.z;
    int pix0 = blockIdx.x * 32;
    int cin0 = blockIdx.y * 32;
    int tx = threadIdx.x, ty = threadIdx.y;  // 32 x 8
#pragma unroll
    for (int k = 0; k < 4; k++) {
        int cin = cin0 + ty + k * 8;
        int pix = pix0 + tx;
        float v = 0.0f;
        if (pix < HW_) v = x[(b * CIN_ + cin) * HW_ + pix];
        tile[ty + k * 8][tx] = v;
    }
    __syncthreads();
#pragma unroll
    for (int k = 0; k < 4; k++) {
        int pix = pix0 + ty + k * 8;
        int cin = cin0 + tx;
        if (pix < HW_) g_xt[(b * HW_ + pix) * CIN_ + cin] = tile[tx][ty + k * 8];
    }
}

// ---------------- setup kernel 2: comb -> bf16 hi/lo, [nf][o][cin] ----------------
__global__ void k_comb(const float* __restrict__ comb) {
    int t = blockIdx.x * 256 + threadIdx.x;   // over NCHUNK*COUT_*KC = 262144
    int cin = t & 63;
    int o   = (t >> 6) & 255;
    int nf  = t >> 14;
    float v = comb[o * K_ + cin * NF_ + nf];
    __nv_bfloat16 h = __float2bfloat16(v);
    float l = v - __bfloat162float(h);
    g_cb_hi[t] = h;
    g_cb_lo[t] = __float2bfloat16(l);
}

// ---------------- setup kernel 3: bilinear gather table ----------------
__device__ __forceinline__ void make_corner(int ix, int iy, float w, int& off, float& wo) {
    int cx = min(max(ix, 0), H_);
    int cy = min(max(iy, 0), W_);
    if (cx < H_ && cy < W_) { off = cx * W_ + cy; wo = w; }
    else                    { off = 0;            wo = 0.0f; }
}
__global__ void k_table(const float* __restrict__ flow) {
    int t = blockIdx.x * 128 + threadIdx.x;
    if (t >= NF_ * HW_) return;
    int pix = t % HW_;
    int i = pix / W_, j = pix % W_;
    float f0 = flow[2 * t + 0];
    float f1 = flow[2 * t + 1];
    float ixf = (float)i + f0;
    float iyf = (float)j + f1;
    float bxf = floorf(ixf), byf = floorf(iyf);
    float s  = ixf - bxf;
    float tt = iyf - byf;
    int bx = (int)bxf, by = (int)byf;
    // NOTE: w10 = s*(1-t) replicates the reference's (intentional) bug.
    float w00 = (1.0f - s) * (1.0f - tt);
    float w01 = s * (1.0f - tt);
    float w10 = s * (1.0f - tt);
    float w11 = s * tt;
    int4 off; float4 wv;
    make_corner(bx,     by,     w00, off.x, wv.x);
    make_corner(bx + 1, by,     w01, off.y, wv.y);
    make_corner(bx,     by + 1, w10, off.z, wv.z);
    make_corner(bx + 1, by + 1, w11, off.w, wv.w);
    g_off[t] = off;
    g_w[t]   = wv;
}

// ---------------- fused gather + mma.sync bf16x3 GEMM ----------------
__global__ __launch_bounds__(256, 2) void k_gemm(const float* __restrict__ bias,
                                                 float* __restrict__ out) {
    extern __shared__ __align__(1024) char smem[];
    const uint32_t sbase = smem_u32(smem);
    const int tid  = threadIdx.x;
    const int wid  = tid >> 5;
    const int lane = tid & 31;
    const int m0   = blockIdx.x * BM;

    ((float*)(smem + OFF_BIAS))[tid] = bias[tid];

    // ---- build-thread mapping: lane16 covers cin quads, rslot covers rows ----
    const int lane16 = tid & 15;
    const int rslot  = tid >> 4;
    const float* xp[4];
    int ppix[4];
    uint32_t a_addr[4];
#pragma unroll
    for (int rr = 0; rr < 4; rr++) {
        int row = rslot + rr * 16;          // 0..63
        int rg  = m0 + row;
        int b   = rg / HW_;
        int pix = rg - b * HW_;
        ppix[rr] = pix;
        xp[rr]   = g_xt + (size_t)b * (HW_ * CIN_) + lane16 * 4;
        a_addr[rr] = (uint32_t)row * RSTRIDE + (uint32_t)lane16 * 8;
    }

    // ---- warp coords: 2 M-warps x 4 N-warps, warp tile 32x64 ----
    const int mw = wid & 1;
    const int nw = wid >> 1;

    // ldmatrix lane-address bases (k-step adds +32B)
    uint32_t aHiB[2], aLoB[2];
#pragma unroll
    for (int mi = 0; mi < 2; mi++) {
        uint32_t off = (uint32_t)(mw * 32 + mi * 16 + (lane & 15)) * RSTRIDE
                     + (uint32_t)(lane >> 4) * 16;
        aHiB[mi] = sbase + OFF_AHI + off;
        aLoB[mi] = sbase + OFF_ALO + off;
    }
    uint32_t bHiB[4], bLoB[4];
#pragma unroll
    for (int nn = 0; nn < 4; nn++) {
        uint32_t off = (uint32_t)(nw * 64 + nn * 16 + ((lane >> 4) << 3) + (lane & 7)) * RSTRIDE
                     + (uint32_t)((lane >> 3) & 1) * 16;
        bHiB[nn] = sbase + OFF_BHI + off;
        bLoB[nn] = sbase + OFF_BLO + off;
    }

    float acc[2][8][4];
#pragma unroll
    for (int i = 0; i < 2; i++)
#pragma unroll
        for (int j = 0; j < 8; j++)
#pragma unroll
            for (int k = 0; k < 4; k++) acc[i][j][k] = 0.0f;

    for (int c = 0; c < NCHUNK; c++) {
        __syncthreads();   // previous chunk's smem reads complete

        // ---- build A tile: bilinear gather -> bf16 hi/lo ----
#pragma unroll
        for (int rr = 0; rr < 4; rr++) {
            int t = c * HW_ + ppix[rr];
            int4   of = g_off[t];
            float4 w  = g_w[t];
            const float* p = xp[rr];
            float4 v0 = *(const float4*)(p + of.x * CIN_);
            float4 v1 = *(const float4*)(p + of.y * CIN_);
            float4 v2 = *(const float4*)(p + of.z * CIN_);
            float4 v3 = *(const float4*)(p + of.w * CIN_);
            float f0 = w.x * v0.x + w.y * v1.x + w.z * v2.x + w.w * v3.x;
            float f1 = w.x * v0.y + w.y * v1.y + w.z * v2.y + w.w * v3.y;
            float f2 = w.x * v0.z + w.y * v1.z + w.z * v2.z + w.w * v3.z;
            float f3 = w.x * v0.w + w.y * v1.w + w.z * v2.w + w.w * v3.w;
            __nv_bfloat16 h0 = __float2bfloat16(f0), h1 = __float2bfloat16(f1);
            __nv_bfloat16 h2 = __float2bfloat16(f2), h3 = __float2bfloat16(f3);
            __nv_bfloat16 l0 = __float2bfloat16(f0 - __bfloat162float(h0));
            __nv_bfloat16 l1 = __float2bfloat16(f1 - __bfloat162float(h1));
            __nv_bfloat16 l2 = __float2bfloat16(f2 - __bfloat162float(h2));
            __nv_bfloat16 l3 = __float2bfloat16(f3 - __bfloat162float(h3));
            __nv_bfloat162 hp0 = __halves2bfloat162(h0, h1);
            __nv_bfloat162 hp1 = __halves2bfloat162(h2, h3);
            __nv_bfloat162 lp0 = __halves2bfloat162(l0, l1);
            __nv_bfloat162 lp1 = __halves2bfloat162(l2, l3);
            sts_v2(sbase + OFF_AHI + a_addr[rr],
                   *reinterpret_cast<uint32_t*>(&hp0), *reinterpret_cast<uint32_t*>(&hp1));
            sts_v2(sbase + OFF_ALO + a_addr[rr],
                   *reinterpret_cast<uint32_t*>(&lp0), *reinterpret_cast<uint32_t*>(&lp1));
        }

        // ---- copy B tile: row tid (256 rows), 64 bf16 each ----
        {
            const uint4* shi = (const uint4*)(g_cb_hi + (size_t)c * 16384 + tid * 64);
            const uint4* slo = (const uint4*)(g_cb_lo + (size_t)c * 16384 + tid * 64);
            uint4* dhi = (uint4*)(smem + OFF_BHI + tid * RSTRIDE);
            uint4* dlo = (uint4*)(smem + OFF_BLO + tid * RSTRIDE);
#pragma unroll
            for (int i = 0; i < 8; i++) dhi[i] = shi[i];
#pragma unroll
            for (int i = 0; i < 8; i++) dlo[i] = slo[i];
        }

        __syncthreads();

        // ---- MMA: 4 k-steps x (2 A-frag sets, 4 B-pairs) x 3 passes ----
#pragma unroll
        for (int ks = 0; ks < 4; ks++) {
            uint32_t ah[2][4], al[2][4];
#pragma unroll
            for (int mi = 0; mi < 2; mi++) {
                ldm_x4(ah[mi][0], ah[mi][1], ah[mi][2], ah[mi][3], aHiB[mi] + ks * 32);
                ldm_x4(al[mi][0], al[mi][1], al[mi][2], al[mi][3], aLoB[mi] + ks * 32);
            }
#pragma unroll
            for (int nn = 0; nn < 4; nn++) {
                uint32_t bh0, bh1, bh2, bh3, bl0, bl1, bl2, bl3;
                ldm_x4(bh0, bh1, bh2, bh3, bHiB[nn] + ks * 32);
                ldm_x4(bl0, bl1, bl2, bl3, bLoB[nn] + ks * 32);
#pragma unroll
                for (int mi = 0; mi < 2; mi++) {
                    mma_bf16(acc[mi][2 * nn],     ah[mi][0], ah[mi][1], ah[mi][2], ah[mi][3], bh0, bh1);
                    mma_bf16(acc[mi][2 * nn + 1], ah[mi][0], ah[mi][1], ah[mi][2], ah[mi][3], bh2, bh3);
                    mma_bf16(acc[mi][2 * nn],     ah[mi][0], ah[mi][1], ah[mi][2], ah[mi][3], bl0, bl1);
                    mma_bf16(acc[mi][2 * nn + 1], ah[mi][0], ah[mi][1], ah[mi][2], ah[mi][3], bl2, bl3);
                    mma_bf16(acc[mi][2 * nn],     al[mi][0], al[mi][1], al[mi][2], al[mi][3], bh0, bh1);
                    mma_bf16(acc[mi][2 * nn + 1], al[mi][0], al[mi][1], al[mi][2], al[mi][3], bh2, bh3);
                }
            }
        }
    }

    // ---- epilogue: += bias, write out[b][o][pix] ----
    const float* sb = (const float*)(smem + OFF_BIAS);
#pragma unroll
    for (int mi = 0; mi < 2; mi++) {
#pragma unroll
        for (int ni = 0; ni < 8; ni++) {
            int row = mw * 32 + mi * 16 + (lane >> 2);
            int o   = nw * 64 + ni * 8 + (lane & 3) * 2;
            int r0  = m0 + row;
            int r1  = r0 + 8;
            int b0  = r0 / HW_, pix0 = r0 - b0 * HW_;
            int b1  = r1 / HW_, pix1 = r1 - b1 * HW_;
            float* o0 = out + ((size_t)b0 * COUT_ + o) * HW_ + pix0;
            float* o1 = out + ((size_t)b1 * COUT_ + o) * HW_ + pix1;
            o0[0]        = acc[mi][ni][0] + sb[o];
            o0[HW_]      = acc[mi][ni][1] + sb[o + 1];
            o1[0]        = acc[mi][ni][2] + sb[o];
            o1[HW_]      = acc[mi][ni][3] + sb[o + 1];
        }
    }
}

// ---------------- launch ----------------
extern "C" void kernel_launch(void* const* d_in, const int* in_sizes, int n_in,
                              void* d_out, int out_size) {
    const float* x    = nullptr;
    const float* flow = nullptr;
    const float* comb = nullptr;
    const float* bias = nullptr;
    for (int i = 0; i < n_in; i++) {
        switch (in_sizes[i]) {
            case B_ * CIN_ * HW_: x    = (const float*)d_in[i]; break;  // 2,048,000
            case NF_ * HW_ * 2:   flow = (const float*)d_in[i]; break;  // 12,800
            case COUT_ * K_:      comb = (const float*)d_in[i]; break;  // 262,144
            case COUT_:           bias = (const float*)d_in[i]; break;  // 256
            default: break;
        }
    }
    float* out = (float*)d_out;

    // setup
    {
        dim3 blk(32, 8);
        dim3 grd((HW_ + 31) / 32, CIN_ / 32, B_);
        k_transpose_x<<<grd, blk>>>(x);
    }
    k_comb<<<(NCHUNK * COUT_ * KC) / 256, 256>>>(comb);
    k_table<<<(NF_ * HW_ + 127) / 128, 128>>>(flow);

    // fused gather + mma.sync GEMM
    cudaFuncSetAttribute(k_gemm, cudaFuncAttributeMaxDynamicSharedMemorySize, SMEM_TOTAL);
    k_gemm<<<M_ / BM, 256, SMEM_TOTAL>>>(bias, out);
}

// round 17
// speedup vs baseline: 2.1658x; 1.1195x over previous
#include <cuda_runtime.h>
#include <cuda_bf16.h>
#include <cstdint>

// Problem constants
#define B_    128
#define CIN_  64
#define NF_   16
#define COUT_ 256
#define H_    20
#define W_    20
#define HW_   400
#define M_    (B_*HW_)    // 51200
#define K_    (CIN_*NF_)  // 1024

// Tile config
#define BM    128         // rows per CTA
#define BN    256         // full COUT
#define KC    64          // K chunk = one nf
#define NCHUNK 16
#define RSTRIDE 144       // smem row stride bytes (72 bf16: 64 data + 8 pad)

// SMEM layout (bytes)
#define OFF_BIAS 0                        // 256 floats = 1024
#define OFF_AHI  1024                     // 128 rows x 144B = 18432
#define OFF_ALO  (OFF_AHI + 18432)
#define OFF_BHI  (OFF_ALO + 18432)        // 256 rows x 144B = 36864
#define OFF_BLO  (OFF_BHI + 36864)
#define SMEM_TOTAL (OFF_BLO + 36864)      // 111616 B

// ---------------- scratch (static __device__, no allocations) ----------------
__device__ __align__(16) float  g_xt[B_*HW_*CIN_];          // x transposed: [b][pix][cin]
__device__ __align__(16) __nv_bfloat16 g_cb_hi[NCHUNK*COUT_*KC]; // comb hi: [nf][o][cin]
__device__ __align__(16) __nv_bfloat16 g_cb_lo[NCHUNK*COUT_*KC]; // comb lo
__device__ __align__(16) int4   g_off[NF_*HW_];             // 4 gather offsets per (nf,pix)
__device__ __align__(16) float4 g_w[NF_*HW_];               // 4 bilinear weights per (nf,pix)

// ---------------- PTX helpers ----------------
__device__ __forceinline__ uint32_t smem_u32(const void* p) {
    uint32_t a;
    asm("{ .reg .u64 t; cvta.to.shared.u64 t, %1; cvt.u32.u64 %0, t; }" : "=r"(a) : "l"(p));
    return a;
}
__device__ __forceinline__ void ldm_x4(uint32_t& r0, uint32_t& r1, uint32_t& r2, uint32_t& r3,
                                       uint32_t addr) {
    asm volatile("ldmatrix.sync.aligned.m8n8.x4.shared.b16 {%0,%1,%2,%3}, [%4];"
                 : "=r"(r0), "=r"(r1), "=r"(r2), "=r"(r3) : "r"(addr));
}
__device__ __forceinline__ void mma_bf16(float* c, uint32_t a0, uint32_t a1, uint32_t a2,
                                         uint32_t a3, uint32_t b0, uint32_t b1) {
    asm volatile(
        "mma.sync.aligned.m16n8k16.row.col.f32.bf16.bf16.f32 "
        "{%0,%1,%2,%3}, {%4,%5,%6,%7}, {%8,%9}, {%0,%1,%2,%3};"
        : "+f"(c[0]), "+f"(c[1]), "+f"(c[2]), "+f"(c[3])
        : "r"(a0), "r"(a1), "r"(a2), "r"(a3), "r"(b0), "r"(b1));
}
__device__ __forceinline__ void sts_v2(uint32_t addr, uint32_t a, uint32_t b) {
    asm volatile("st.shared.v2.b32 [%0], {%1, %2};" :: "r"(addr), "r"(a), "r"(b) : "memory");
}

// ---------------- setup kernel 1: transpose x -> x_t[b][pix][cin] ----------------
__global__ void k_transpose_x(const float* __restrict__ x) {
    __shared__ float tile[32][33];
    int b    = blockIdx.z;
    int pix0 = blockIdx.x * 32;
    int cin0 = blockIdx.y * 32;
    int tx = threadIdx.x, ty = threadIdx.y;  // 32 x 8
#pragma unroll
    for (int k = 0; k < 4; k++) {
        int cin = cin0 + ty + k * 8;
        int pix = pix0 + tx;
        float v = 0.0f;
        if (pix < HW_) v = x[(b * CIN_ + cin) * HW_ + pix];
        tile[ty + k * 8][tx] = v;
    }
    __syncthreads();
#pragma unroll
    for (int k = 0; k < 4; k++) {
        int pix = pix0 + ty + k * 8;
        int cin = cin0 + tx;
        if (pix < HW_) g_xt[(b * HW_ + pix) * CIN_ + cin] = tile[tx][ty + k * 8];
    }
}

// ---------------- setup kernel 2: comb -> bf16 hi/lo, [nf][o][cin] ----------------
__global__ void k_comb(const float* __restrict__ comb) {
    int t = blockIdx.x * 256 + threadIdx.x;   // over NCHUNK*COUT_*KC = 262144
    int cin = t & 63;
    int o   = (t >> 6) & 255;
    int nf  = t >> 14;
    float v = comb[o * K_ + cin * NF_ + nf];
    __nv_bfloat16 h = __float2bfloat16(v);
    float l = v - __bfloat162float(h);
    g_cb_hi[t] = h;
    g_cb_lo[t] = __float2bfloat16(l);
}

// ---------------- setup kernel 3: bilinear gather table ----------------
__device__ __forceinline__ void make_corner(int ix, int iy, float w, int& off, float& wo) {
    int cx = min(max(ix, 0), H_);
    int cy = min(max(iy, 0), W_);
    if (cx < H_ && cy < W_) { off = cx * W_ + cy; wo = w; }
    else                    { off = 0;            wo = 0.0f; }
}
__global__ void k_table(const float* __restrict__ flow) {
    int t = blockIdx.x * 128 + threadIdx.x;
    if (t >= NF_ * HW_) return;
    int pix = t % HW_;
    int i = pix / W_, j = pix % W_;
    float f0 = flow[2 * t + 0];
    float f1 = flow[2 * t + 1];
    float ixf = (float)i + f0;
    float iyf = (float)j + f1;
    float bxf = floorf(ixf), byf = floorf(iyf);
    float s  = ixf - bxf;
    float tt = iyf - byf;
    int bx = (int)bxf, by = (int)byf;
    // NOTE: w10 = s*(1-t) replicates the reference's (intentional) bug.
    float w00 = (1.0f - s) * (1.0f - tt);
    float w01 = s * (1.0f - tt);
    float w10 = s * (1.0f - tt);
    float w11 = s * tt;
    int4 off; float4 wv;
    make_corner(bx,     by,     w00, off.x, wv.x);
    make_corner(bx + 1, by,     w01, off.y, wv.y);
    make_corner(bx,     by + 1, w10, off.z, wv.z);
    make_corner(bx + 1, by + 1, w11, off.w, wv.w);
    g_off[t] = off;
    g_w[t]   = wv;
}

// ---------------- fused gather + mma.sync bf16x3 GEMM (64x64 warp tiles) ----------------
__global__ __launch_bounds__(256, 1) void k_gemm(const float* __restrict__ bias,
                                                 float* __restrict__ out) {
    extern __shared__ __align__(1024) char smem[];
    const uint32_t sbase = smem_u32(smem);
    const int tid  = threadIdx.x;
    const int wid  = tid >> 5;
    const int lane = tid & 31;
    const int m0   = blockIdx.x * BM;

    ((float*)(smem + OFF_BIAS))[tid] = bias[tid];

    // ---- build-thread mapping: lane16 covers cin quads, rslot covers rows ----
    const int lane16 = tid & 15;
    const int rslot  = tid >> 4;
    const float* xp[8];
    int ppix[8];
    uint32_t a_addr[8];
#pragma unroll
    for (int rr = 0; rr < 8; rr++) {
        int row = rslot + rr * 16;          // 0..127
        int rg  = m0 + row;
        int b   = rg / HW_;
        int pix = rg - b * HW_;
        ppix[rr] = pix;
        xp[rr]   = g_xt + (size_t)b * (HW_ * CIN_) + lane16 * 4;
        a_addr[rr] = (uint32_t)row * RSTRIDE + (uint32_t)lane16 * 8;
    }

    // ---- warp coords: 2 M-warps x 4 N-warps, warp tile 64x64 ----
    const int mw = wid & 1;
    const int nw = wid >> 1;

    // ldmatrix lane-address bases (k-step adds +32B)
    uint32_t aHiB[4], aLoB[4];
#pragma unroll
    for (int mi = 0; mi < 4; mi++) {
        uint32_t off = (uint32_t)(mw * 64 + mi * 16 + (lane & 15)) * RSTRIDE
                     + (uint32_t)(lane >> 4) * 16;
        aHiB[mi] = sbase + OFF_AHI + off;
        aLoB[mi] = sbase + OFF_ALO + off;
    }
    uint32_t bHiB[4], bLoB[4];
#pragma unroll
    for (int nn = 0; nn < 4; nn++) {
        uint32_t off = (uint32_t)(nw * 64 + nn * 16 + ((lane >> 4) << 3) + (lane & 7)) * RSTRIDE
                     + (uint32_t)((lane >> 3) & 1) * 16;
        bHiB[nn] = sbase + OFF_BHI + off;
        bLoB[nn] = sbase + OFF_BLO + off;
    }

    float acc[4][8][4];
#pragma unroll
    for (int i = 0; i < 4; i++)
#pragma unroll
        for (int j = 0; j < 8; j++)
#pragma unroll
            for (int k = 0; k < 4; k++) acc[i][j][k] = 0.0f;

    for (int c = 0; c < NCHUNK; c++) {
        __syncthreads();   // previous chunk's smem reads complete

        // ---- build A tile: bilinear gather -> bf16 hi/lo ----
#pragma unroll
        for (int rr = 0; rr < 8; rr++) {
            int t = c * HW_ + ppix[rr];
            int4   of = g_off[t];
            float4 w  = g_w[t];
            const float* p = xp[rr];
            float4 v0 = *(const float4*)(p + of.x * CIN_);
            float4 v1 = *(const float4*)(p + of.y * CIN_);
            float4 v2 = *(const float4*)(p + of.z * CIN_);
            float4 v3 = *(const float4*)(p + of.w * CIN_);
            float f0 = w.x * v0.x + w.y * v1.x + w.z * v2.x + w.w * v3.x;
            float f1 = w.x * v0.y + w.y * v1.y + w.z * v2.y + w.w * v3.y;
            float f2 = w.x * v0.z + w.y * v1.z + w.z * v2.z + w.w * v3.z;
            float f3 = w.x * v0.w + w.y * v1.w + w.z * v2.w + w.w * v3.w;
            __nv_bfloat16 h0 = __float2bfloat16(f0), h1 = __float2bfloat16(f1);
            __nv_bfloat16 h2 = __float2bfloat16(f2), h3 = __float2bfloat16(f3);
            __nv_bfloat16 l0 = __float2bfloat16(f0 - __bfloat162float(h0));
            __nv_bfloat16 l1 = __float2bfloat16(f1 - __bfloat162float(h1));
            __nv_bfloat16 l2 = __float2bfloat16(f2 - __bfloat162float(h2));
            __nv_bfloat16 l3 = __float2bfloat16(f3 - __bfloat162float(h3));
            __nv_bfloat162 hp0 = __halves2bfloat162(h0, h1);
            __nv_bfloat162 hp1 = __halves2bfloat162(h2, h3);
            __nv_bfloat162 lp0 = __halves2bfloat162(l0, l1);
            __nv_bfloat162 lp1 = __halves2bfloat162(l2, l3);
            sts_v2(sbase + OFF_AHI + a_addr[rr],
                   *reinterpret_cast<uint32_t*>(&hp0), *reinterpret_cast<uint32_t*>(&hp1));
            sts_v2(sbase + OFF_ALO + a_addr[rr],
                   *reinterpret_cast<uint32_t*>(&lp0), *reinterpret_cast<uint32_t*>(&lp1));
        }

        // ---- copy B tile: row tid (256 rows), 64 bf16 each ----
        {
            const uint4* shi = (const uint4*)(g_cb_hi + (size_t)c * 16384 + tid * 64);
            const uint4* slo = (const uint4*)(g_cb_lo + (size_t)c * 16384 + tid * 64);
            uint4* dhi = (uint4*)(smem + OFF_BHI + tid * RSTRIDE);
            uint4* dlo = (uint4*)(smem + OFF_BLO + tid * RSTRIDE);
#pragma unroll
            for (int i = 0; i < 8; i++) dhi[i] = shi[i];
#pragma unroll
            for (int i = 0; i < 8; i++) dlo[i] = slo[i];
        }

        __syncthreads();

        // ---- MMA: 4 k-steps x (4 A-frag sets, 4 B-pairs) x 3 passes ----
#pragma unroll
        for (int ks = 0; ks < 4; ks++) {
            uint32_t ah[4][4], al[4][4];
#pragma unroll
            for (int mi = 0; mi < 4; mi++) {
                ldm_x4(ah[mi][0], ah[mi][1], ah[mi][2], ah[mi][3], aHiB[mi] + ks * 32);
                ldm_x4(al[mi][0], al[mi][1], al[mi][2], al[mi][3], aLoB[mi] + ks * 32);
            }
#pragma unroll
            for (int nn = 0; nn < 4; nn++) {
                uint32_t bh0, bh1, bh2, bh3, bl0, bl1, bl2, bl3;
                ldm_x4(bh0, bh1, bh2, bh3, bHiB[nn] + ks * 32);
                ldm_x4(bl0, bl1, bl2, bl3, bLoB[nn] + ks * 32);
#pragma unroll
                for (int mi = 0; mi < 4; mi++) {
                    mma_bf16(acc[mi][2 * nn],     ah[mi][0], ah[mi][1], ah[mi][2], ah[mi][3], bh0, bh1);
                    mma_bf16(acc[mi][2 * nn + 1], ah[mi][0], ah[mi][1], ah[mi][2], ah[mi][3], bh2, bh3);
                    mma_bf16(acc[mi][2 * nn],     ah[mi][0], ah[mi][1], ah[mi][2], ah[mi][3], bl0, bl1);
                    mma_bf16(acc[mi][2 * nn + 1], ah[mi][0], ah[mi][1], ah[mi][2], ah[mi][3], bl2, bl3);
                    mma_bf16(acc[mi][2 * nn],     al[mi][0], al[mi][1], al[mi][2], al[mi][3], bh0, bh1);
                    mma_bf16(acc[mi][2 * nn + 1], al[mi][0], al[mi][1], al[mi][2], al[mi][3], bh2, bh3);
                }
            }
        }
    }

    // ---- epilogue: += bias, write out[b][o][pix] ----
    const float* sb = (const float*)(smem + OFF_BIAS);
#pragma unroll
    for (int mi = 0; mi < 4; mi++) {
#pragma unroll
        for (int ni = 0; ni < 8; ni++) {
            int row = mw * 64 + mi * 16 + (lane >> 2);
            int o   = nw * 64 + ni * 8 + (lane & 3) * 2;
            int r0  = m0 + row;
            int r1  = r0 + 8;
            int b0  = r0 / HW_, pix0 = r0 - b0 * HW_;
            int b1  = r1 / HW_, pix1 = r1 - b1 * HW_;
            float* o0 = out + ((size_t)b0 * COUT_ + o) * HW_ + pix0;
            float* o1 = out + ((size_t)b1 * COUT_ + o) * HW_ + pix1;
            o0[0]   = acc[mi][ni][0] + sb[o];
            o0[HW_] = acc[mi][ni][1] + sb[o + 1];
            o1[0]   = acc[mi][ni][2] + sb[o];
            o1[HW_] = acc[mi][ni][3] + sb[o + 1];
        }
    }
}

// ---------------- launch ----------------
extern "C" void kernel_launch(void* const* d_in, const int* in_sizes, int n_in,
                              void* d_out, int out_size) {
    const float* x    = nullptr;
    const float* flow = nullptr;
    const float* comb = nullptr;
    const float* bias = nullptr;
    for (int i = 0; i < n_in; i++) {
        switch (in_sizes[i]) {
            case B_ * CIN_ * HW_: x    = (const float*)d_in[i]; break;  // 2,048,000
            case NF_ * HW_ * 2:   flow = (const float*)d_in[i]; break;  // 12,800
            case COUT_ * K_:      comb = (const float*)d_in[i]; break;  // 262,144
            case COUT_:           bias = (const float*)d_in[i]; break;  // 256
            default: break;
        }
    }
    float* out = (float*)d_out;

    // setup
    {
        dim3 blk(32, 8);
        dim3 grd((HW_ + 31) / 32, CIN_ / 32, B_);
        k_transpose_x<<<grd, blk>>>(x);
    }
    k_comb<<<(NCHUNK * COUT_ * KC) / 256, 256>>>(comb);
    k_table<<<(NF_ * HW_ + 127) / 128, 128>>>(flow);

    // fused gather + mma.sync GEMM
    cudaFuncSetAttribute(k_gemm, cudaFuncAttributeMaxDynamicSharedMemorySize, SMEM_TOTAL);
    k_gemm<<<M_ / BM, 256, SMEM_TOTAL>>>(bias, out);
}